// round 3
// baseline (speedup 1.0000x reference)
#include <cuda_runtime.h>
#include <cstdint>

#define NVOX   (64*128*128)        // 1048576 voxels per image
#define NB     2
#define NC     32
#define PCAP   2048
#define NCAP   12288
#define COLCAP (PCAP+NCAP)         // 14336
#define CHUNK  128                 // columns per k_main block (finer for balance)
#define NYCH   (COLCAP/CHUNK)      // 112 worst-case column chunks
#define NROWS  (NB*64*128)         // 16384 (img,d,h) rows of 128 voxels

typedef unsigned long long ull;

// ---------------- device scratch (no allocations allowed) ----------------
__device__ unsigned g_bf[NROWS*4];     // fg bits,   1 bit/voxel, 4 words/row
__device__ unsigned g_bw[NROWS*4];     // W-dilated
__device__ unsigned g_bh[NROWS*4];     // W+H-dilated
__device__ int    g_cnt[NB][2];
__device__ int    g_done;
__device__ int    g_posIdx[NB][PCAP];
__device__ int    g_negIdx[NB][NCAP];
__device__ float4 g_posF[NB][PCAP][8];    // 32 floats per row, L2-normalized
__device__ float4 g_negF[NB][NCAP][8];
__device__ float  g_acc[NB][PCAP][2];     // per-anchor (num, neg) accumulators
__device__ float  g_imgLoss[NB];
__device__ int    g_imgValid[NB];

// idx helper: (plane, h, word) -> word index; plane = img*64 + d
__device__ __forceinline__ int bidx(int pl, int h, int w) { return pl*512 + h*4 + w; }

// ---------------- stage 1: fg bitmask + W-dilation (fused) ------------------
// 8 warps/block, 1 warp per (img,d,h) row of 128 voxels.  Blocks 0..31 also
// zero the per-anchor accumulators (consumed only by k_main, which is ordered
// after this kernel on the stream).
__global__ void k_pack(const int* __restrict__ lab) {
    int warp = threadIdx.x >> 5, lane = threadIdx.x & 31;
    int row  = blockIdx.x * 8 + warp;            // [0, NROWS)
    __shared__ unsigned srow[8][4];
    if (lane < 4) srow[warp][lane] = 0;
    __syncwarp();
    int4 l = *reinterpret_cast<const int4*>(lab + (size_t)row*128 + lane*4);
    unsigned nib = (unsigned)(l.x > 0) | ((unsigned)(l.y > 0) << 1)
                 | ((unsigned)(l.z > 0) << 2) | ((unsigned)(l.w > 0) << 3);
    if (nib) atomicOr(&srow[warp][lane >> 3], nib << ((lane & 7) * 4));
    __syncwarp();
    if (lane < 4) {
        unsigned f  = srow[warp][lane];
        unsigned fl = (lane > 0) ? srow[warp][lane-1] : 0u;
        unsigned fr = (lane < 3) ? srow[warp][lane+1] : 0u;
        unsigned dil = f;
        #pragma unroll
        for (int k = 1; k <= 5; ++k) {
            dil |= __funnelshift_r(f, fr, k);    // 128-bit >> k, this word
            dil |= __funnelshift_l(fl, f, k);    // 128-bit << k, this word
        }
        g_bf[row*4 + lane] = f;
        g_bw[row*4 + lane] = dil;
    }
    if (blockIdx.x < 32) {                       // zero g_acc: 8192 floats
        ((float*)g_acc)[blockIdx.x * 256 + threadIdx.x] = 0.f;
    }
    if (blockIdx.x == 0 && threadIdx.x == 0) {
        g_cnt[0][0] = g_cnt[0][1] = g_cnt[1][0] = g_cnt[1][1] = 0;
        g_done = 0;
    }
}

// ---------------- stage 2: H-dilation on bit-words --------------------------
__global__ void k_dilh() {
    int t = blockIdx.x * 256 + threadIdx.x;      // [0, NROWS*4) = 65536
    int w  = t & 3;
    int h  = (t >> 2) & 127;
    int pl = t >> 9;
    unsigned acc = 0;
    #pragma unroll
    for (int k = -5; k <= 5; ++k) {
        int hh = h + k;
        if ((unsigned)hh < 128u) acc |= g_bw[bidx(pl, hh, w)];
    }
    g_bh[bidx(pl, h, w)] = acc;
}

// ---------------- stage 3: D-dilation + rim + atomic emit -------------------
__global__ void k_demit() {
    int t = blockIdx.x * 256 + threadIdx.x;      // 65536
    int w   = t & 3;
    int h   = (t >> 2) & 127;
    int pl  = t >> 9;
    int img = pl >> 6, d = pl & 63;
    unsigned acc = 0;
    #pragma unroll
    for (int k = -5; k <= 5; ++k) {
        int dd = d + k;
        if ((unsigned)dd < 64u) acc |= g_bh[bidx(img*64 + dd, h, w)];
    }
    unsigned fgw = g_bf[bidx(pl, h, w)];
    unsigned rim = acc & ~fgw;
    int vbase = d*16384 + h*128 + w*32;
    if (fgw) {
        int c = __popc(fgw);
        int base = atomicAdd(&g_cnt[img][0], c);
        unsigned m = fgw;
        while (m) {
            int b = __ffs(m) - 1; m &= m - 1;
            if (base < PCAP) g_posIdx[img][base] = vbase + b;
            base++;
        }
    }
    if (rim) {
        int c = __popc(rim);
        int base = atomicAdd(&g_cnt[img][1], c);
        unsigned m = rim;
        while (m) {
            int b = __ffs(m) - 1; m &= m - 1;
            if (base < NCAP) g_negIdx[img][base] = vbase + b;
            base++;
        }
    }
}

// ---------------- stage 4: gather + L2-normalize selected rows --------------
// 8 threads per row (one channel-slot each, 4 channels per thread); 32 rows
// per block. Warp = one slot x 32 adjacent rows -> same-channel coalesced
// loads, 4 independent loads in flight per thread.
__global__ void k_gather(const float* __restrict__ feats) {
    int lane = threadIdx.x & 31;                 // row within block
    int slot = threadIdx.x >> 5;                 // channel slot 0..7
    int gs   = blockIdx.x * 32 + lane;           // global selection index
    int img  = gs / COLCAP;                      // uniform per block (14336%32==0)
    int s    = gs - img * COLCAP;
    int posCnt = min(g_cnt[img][0], PCAP);
    int negCnt = min(g_cnt[img][1], NCAP);
    bool valid; int n; float* dst;
    if (s < PCAP) {
        valid = (s < posCnt);
        n   = valid ? g_posIdx[img][s] : 0;
        dst = (float*)&g_posF[img][s][0];
    } else {
        int j = s - PCAP;
        valid = (j < negCnt);
        n   = valid ? g_negIdx[img][j] : 0;
        dst = (float*)&g_negF[img][j][0];
    }
    const float* f = feats + (size_t)img * NC * NVOX + n;
    float v[4]; float ss = 0.f;
    #pragma unroll
    for (int k = 0; k < 4; ++k) {
        int c = slot + 8*k;
        v[k] = valid ? __ldg(f + (size_t)c * NVOX) : 0.f;
        ss += v[k] * v[k];
    }
    __shared__ float red[8][32];
    red[slot][lane] = ss;
    __syncthreads();
    if (slot == 0) {
        float t = 0.f;
        #pragma unroll
        for (int i = 0; i < 8; ++i) t += red[i][lane];
        red[0][lane] = 1.0f / fmaxf(sqrtf(t), 1e-12f);
    }
    __syncthreads();
    if (valid) {
        float sc = red[0][lane];
        #pragma unroll
        for (int k = 0; k < 4; ++k) dst[slot + 8*k] = v[k] * sc;
    }
}

// ---------------- stage 5: main contraction + single-pass softmax sums ------
// 256 anchors/block (2 per thread) x one 128-column tile in SMEM.
// Dot via packed fp32 FFMA2; anchors pre-scaled by 10*log2(e) so the softmax
// exp is a bare exp2f (MUFU.EX2).  Partials atomically accumulated per anchor
// (fp ordering nondeterminism ~1e-7 << 1e-3 tolerance).
__global__ void __launch_bounds__(128, 3) k_main() {
    int img = blockIdx.z;
    int posCnt = min(g_cnt[img][0], PCAP);
    int negCnt = min(g_cnt[img][1], NCAP);
    int nCol = posCnt + negCnt;
    int aBase = blockIdx.x * 256;
    int cBase = blockIdx.y * CHUNK;
    if (aBase >= posCnt || cBase >= nCol) return;
    int tid = threadIdx.x;
    int a0 = aBase + tid, a1 = a0 + 128;

    const float SCALE = 14.4269504088896340f;    // (1/TAU) * log2(e)
    ull kk;
    { float2 sc2 = make_float2(SCALE, SCALE); kk = *reinterpret_cast<ull*>(&sc2); }

    ulonglong2 A0[8], A1[8];
    {
        const ulonglong2* p0 = reinterpret_cast<const ulonglong2*>(&g_posF[img][a0][0]);
        const ulonglong2* p1 = reinterpret_cast<const ulonglong2*>(&g_posF[img][a1][0]);
        #pragma unroll
        for (int u = 0; u < 8; ++u) {
            ulonglong2 x0 = p0[u], x1 = p1[u];
            asm("mul.rn.f32x2 %0, %1, %2;" : "=l"(x0.x) : "l"(x0.x), "l"(kk));
            asm("mul.rn.f32x2 %0, %1, %2;" : "=l"(x0.y) : "l"(x0.y), "l"(kk));
            asm("mul.rn.f32x2 %0, %1, %2;" : "=l"(x1.x) : "l"(x1.x), "l"(kk));
            asm("mul.rn.f32x2 %0, %1, %2;" : "=l"(x1.y) : "l"(x1.y), "l"(kk));
            A0[u] = x0; A1[u] = x1;
        }
    }
    __shared__ float4 s_tile[CHUNK * 8];         // 16 KB
    int tc = min(CHUNK, nCol - cBase);
    if (tid < tc) {
        int g = cBase + tid;
        const float4* src = (g < posCnt) ? &g_posF[img][g][0]
                                         : &g_negF[img][g - posCnt][0];
        #pragma unroll
        for (int u = 0; u < 8; ++u) s_tile[tid*8 + u] = src[u];
    }
    __syncthreads();

    float num0 = 0.f, neg0 = 0.f, num1 = 0.f, neg1 = 0.f;
    #pragma unroll 2
    for (int j = 0; j < tc; ++j) {
        const ulonglong2* cv = reinterpret_cast<const ulonglong2*>(&s_tile[j*8]);
        ull s00 = 0ull, s01 = 0ull, s10 = 0ull, s11 = 0ull;
        #pragma unroll
        for (int u = 0; u < 8; ++u) {
            ulonglong2 v = cv[u];
            asm("fma.rn.f32x2 %0, %1, %2, %0;" : "+l"(s00) : "l"(A0[u].x), "l"(v.x));
            asm("fma.rn.f32x2 %0, %1, %2, %0;" : "+l"(s01) : "l"(A0[u].y), "l"(v.y));
            asm("fma.rn.f32x2 %0, %1, %2, %0;" : "+l"(s10) : "l"(A1[u].x), "l"(v.x));
            asm("fma.rn.f32x2 %0, %1, %2, %0;" : "+l"(s11) : "l"(A1[u].y), "l"(v.y));
        }
        ull t0, t1;
        asm("add.rn.f32x2 %0, %1, %2;" : "=l"(t0) : "l"(s00), "l"(s01));
        asm("add.rn.f32x2 %0, %1, %2;" : "=l"(t1) : "l"(s10), "l"(s11));
        float d0 = __uint_as_float((unsigned)t0) + __uint_as_float((unsigned)(t0 >> 32));
        float d1 = __uint_as_float((unsigned)t1) + __uint_as_float((unsigned)(t1 >> 32));
        float e0 = exp2f(d0);                    // logits pre-scaled
        float e1 = exp2f(d1);
        int jg = cBase + j;
        if (jg < posCnt) {
            if (jg != a0) num0 += e0;
            if (jg != a1) num1 += e1;
        } else { neg0 += e0; neg1 += e1; }
    }
    if (a0 < posCnt) { atomicAdd(&g_acc[img][a0][0], num0); atomicAdd(&g_acc[img][a0][1], neg0); }
    if (a1 < posCnt) { atomicAdd(&g_acc[img][a1][0], num1); atomicAdd(&g_acc[img][a1][1], neg1); }
}

// ---------------- stage 6: per-image reduction + final (fused) --------------
__global__ void k_redfinal(float* out) {
    int img = blockIdx.x;
    int tid = threadIdx.x;
    int posCnt = min(g_cnt[img][0], PCAP);
    int negCnt = min(g_cnt[img][1], NCAP);
    float sum = 0.f, cnt = 0.f;
    for (int a = tid; a < posCnt; a += 256) {
        float num = g_acc[img][a][0];
        float neg = g_acc[img][a][1];
        if (num > 0.f) { sum += log1pf(neg / num); cnt += 1.f; }  // -log(num/(num+neg))
    }
    __shared__ float ss[256], sc[256];
    ss[tid] = sum; sc[tid] = cnt;
    __syncthreads();
    for (int o = 128; o > 0; o >>= 1) {
        if (tid < o) { ss[tid] += ss[tid + o]; sc[tid] += sc[tid + o]; }
        __syncthreads();
    }
    if (tid == 0) {
        g_imgLoss[img]  = ss[0] / fmaxf(sc[0], 1.f);
        g_imgValid[img] = (posCnt >= 2 && negCnt > 0 && sc[0] > 0.f) ? 1 : 0;
        __threadfence();
        int ticket = atomicAdd(&g_done, 1);
        if (ticket == NB - 1) {                   // last image finalizes
            float v0 = g_imgValid[0] ? 1.f : 0.f;
            float v1 = g_imgValid[1] ? 1.f : 0.f;
            float s = g_imgLoss[0]*v0 + g_imgLoss[1]*v1;
            float tot = s / fmaxf(v0 + v1, 1.f);
            out[0] = (v0 + v1 > 0.f) ? tot : 0.f;
        }
    }
}

// ---------------- launch ----------------
extern "C" void kernel_launch(void* const* d_in, const int* in_sizes, int n_in,
                              void* d_out, int out_size) {
    const float* feats = (const float*)d_in[0];
    const int*   lab   = (const int*)d_in[1];
    (void)in_sizes; (void)n_in; (void)out_size;

    k_pack  <<<NROWS/8, 256>>>(lab);
    k_dilh  <<<NROWS*4/256, 256>>>();
    k_demit <<<NROWS*4/256, 256>>>();
    k_gather<<<NB*COLCAP/32, 256>>>(feats);
    k_main  <<<dim3(PCAP/256, NYCH, NB), 128>>>();
    k_redfinal<<<NB, 256>>>((float*)d_out);
}

// round 5
// speedup vs baseline: 1.8620x; 1.8620x over previous
#include <cuda_runtime.h>
#include <cstdint>

#define NVOX   (64*128*128)        // 1048576 voxels per image
#define NB     2
#define NC     32
#define PCAP   2048
#define NCAP   12288
#define COLCAP (PCAP+NCAP)         // 14336
#define CHUNK  256                 // columns per k_main block
#define NYCH   (COLCAP/CHUNK)      // 56 worst-case column chunks
#define NROWS  (NB*64*128)         // 16384 (img,d,h) rows of 128 voxels

typedef unsigned long long ull;

// ---------------- device scratch (no allocations allowed) ----------------
__device__ unsigned g_bf[NROWS*4];     // fg bits,   1 bit/voxel, 4 words/row
__device__ unsigned g_bw[NROWS*4];     // W-dilated
__device__ unsigned g_bh[NROWS*4];     // W+H-dilated
__device__ int    g_cnt[NB][2];
__device__ int    g_done;
__device__ int    g_posIdx[NB][PCAP];
__device__ int    g_negIdx[NB][NCAP];
__device__ float4 g_posF[NB][PCAP][8];    // 32 floats per row, L2-normalized
__device__ float4 g_negF[NB][NCAP][8];
__device__ float  g_acc[NB][PCAP][2];     // per-anchor (num, neg) accumulators
__device__ float  g_imgLoss[NB];
__device__ int    g_imgValid[NB];

// idx helper: (plane, h, word) -> word index; plane = img*64 + d
__device__ __forceinline__ int bidx(int pl, int h, int w) { return pl*512 + h*4 + w; }

// ---------------- stage 1: fg bitmask + W-dilation (fused) ------------------
// 8 warps/block, 1 warp per (img,d,h) row of 128 voxels.  Blocks 0..31 also
// zero the per-anchor accumulators (stream-ordered before k_main).
__global__ void k_pack(const int* __restrict__ lab) {
    int warp = threadIdx.x >> 5, lane = threadIdx.x & 31;
    int row  = blockIdx.x * 8 + warp;            // [0, NROWS)
    __shared__ unsigned srow[8][4];
    if (lane < 4) srow[warp][lane] = 0;
    __syncwarp();
    int4 l = *reinterpret_cast<const int4*>(lab + (size_t)row*128 + lane*4);
    unsigned nib = (unsigned)(l.x > 0) | ((unsigned)(l.y > 0) << 1)
                 | ((unsigned)(l.z > 0) << 2) | ((unsigned)(l.w > 0) << 3);
    if (nib) atomicOr(&srow[warp][lane >> 3], nib << ((lane & 7) * 4));
    __syncwarp();
    if (lane < 4) {
        unsigned f  = srow[warp][lane];
        unsigned fl = (lane > 0) ? srow[warp][lane-1] : 0u;
        unsigned fr = (lane < 3) ? srow[warp][lane+1] : 0u;
        unsigned dil = f;
        #pragma unroll
        for (int k = 1; k <= 5; ++k) {
            dil |= __funnelshift_r(f, fr, k);    // 128-bit >> k, this word
            dil |= __funnelshift_l(fl, f, k);    // 128-bit << k, this word
        }
        g_bf[row*4 + lane] = f;
        g_bw[row*4 + lane] = dil;
    }
    if (blockIdx.x < 32) {                       // zero g_acc: 8192 floats
        ((float*)g_acc)[blockIdx.x * 256 + threadIdx.x] = 0.f;
    }
    if (blockIdx.x == 0 && threadIdx.x == 0) {
        g_cnt[0][0] = g_cnt[0][1] = g_cnt[1][0] = g_cnt[1][1] = 0;
        g_done = 0;
    }
}

// ---------------- stage 2: H-dilation on bit-words --------------------------
__global__ void k_dilh() {
    int t = blockIdx.x * 256 + threadIdx.x;      // [0, NROWS*4) = 65536
    int w  = t & 3;
    int h  = (t >> 2) & 127;
    int pl = t >> 9;
    unsigned acc = 0;
    #pragma unroll
    for (int k = -5; k <= 5; ++k) {
        int hh = h + k;
        if ((unsigned)hh < 128u) acc |= g_bw[bidx(pl, hh, w)];
    }
    g_bh[bidx(pl, h, w)] = acc;
}

// ---------------- stage 3: D-dilation + rim + atomic emit -------------------
__global__ void k_demit() {
    int t = blockIdx.x * 256 + threadIdx.x;      // 65536
    int w   = t & 3;
    int h   = (t >> 2) & 127;
    int pl  = t >> 9;
    int img = pl >> 6, d = pl & 63;
    unsigned acc = 0;
    #pragma unroll
    for (int k = -5; k <= 5; ++k) {
        int dd = d + k;
        if ((unsigned)dd < 64u) acc |= g_bh[bidx(img*64 + dd, h, w)];
    }
    unsigned fgw = g_bf[bidx(pl, h, w)];
    unsigned rim = acc & ~fgw;
    int vbase = d*16384 + h*128 + w*32;
    if (fgw) {
        int c = __popc(fgw);
        int base = atomicAdd(&g_cnt[img][0], c);
        unsigned m = fgw;
        while (m) {
            int b = __ffs(m) - 1; m &= m - 1;
            if (base < PCAP) g_posIdx[img][base] = vbase + b;
            base++;
        }
    }
    if (rim) {
        int c = __popc(rim);
        int base = atomicAdd(&g_cnt[img][1], c);
        unsigned m = rim;
        while (m) {
            int b = __ffs(m) - 1; m &= m - 1;
            if (base < NCAP) g_negIdx[img][base] = vbase + b;
            base++;
        }
    }
}

// ---------------- stage 4: gather + L2-normalize selected rows --------------
// Round-2 form (measured 7.3us): 1 thread per row, 32 independent strided
// loads in flight (good MLP), registers ~47.
__global__ void k_gather(const float* __restrict__ feats) {
    int t = blockIdx.x * 256 + threadIdx.x;
    int img = t / COLCAP;
    if (img >= NB) return;
    int s = t - img * COLCAP;
    int posCnt = min(g_cnt[img][0], PCAP);
    int negCnt = min(g_cnt[img][1], NCAP);
    int n; float4* dst;
    if (s < PCAP) {
        if (s >= posCnt) return;
        n = g_posIdx[img][s]; dst = g_posF[img][s];
    } else {
        int j = s - PCAP;
        if (j >= negCnt) return;
        n = g_negIdx[img][j]; dst = g_negF[img][j];
    }
    const float* f = feats + (size_t)img * NC * NVOX + n;
    float v[NC]; float ss = 0.f;
    #pragma unroll
    for (int c = 0; c < NC; ++c) { v[c] = __ldg(f + (size_t)c * NVOX); ss += v[c]*v[c]; }
    float sc = 1.0f / fmaxf(sqrtf(ss), 1e-12f);
    #pragma unroll
    for (int u = 0; u < 8; ++u)
        dst[u] = make_float4(v[4*u]*sc, v[4*u+1]*sc, v[4*u+2]*sc, v[4*u+3]*sc);
}

// ---------------- stage 5: main contraction + single-pass softmax sums ------
// 256 anchors/block (2 per thread) x one 256-column tile staged once in SMEM
// (32 KB, one __syncthreads).  Dot via packed fp32 FFMA2; anchors pre-scaled
// by (1/TAU)*log2(e) so softmax exp is a bare exp2f (MUFU.EX2).  Per-anchor
// (num,neg) partials accumulated with atomicAdd (REDG; ordering noise ~1e-7).
__global__ void __launch_bounds__(128, 3) k_main() {
    int img = blockIdx.z;
    int posCnt = min(g_cnt[img][0], PCAP);
    int negCnt = min(g_cnt[img][1], NCAP);
    int nCol = posCnt + negCnt;
    int aBase = blockIdx.x * 256;
    int cBase = blockIdx.y * CHUNK;
    if (aBase >= posCnt || cBase >= nCol) return;
    int tid = threadIdx.x;
    int a0 = aBase + tid, a1 = a0 + 128;

    const float SCALE = 14.4269504088896340f;    // (1/TAU) * log2(e)
    ull kk;
    { float2 sc2 = make_float2(SCALE, SCALE); kk = *reinterpret_cast<ull*>(&sc2); }

    ulonglong2 A0[8], A1[8];
    {
        const ulonglong2* p0 = reinterpret_cast<const ulonglong2*>(&g_posF[img][a0][0]);
        const ulonglong2* p1 = reinterpret_cast<const ulonglong2*>(&g_posF[img][a1][0]);
        #pragma unroll
        for (int u = 0; u < 8; ++u) {
            ulonglong2 x0 = p0[u], x1 = p1[u];
            asm("mul.rn.f32x2 %0, %1, %2;" : "=l"(x0.x) : "l"(x0.x), "l"(kk));
            asm("mul.rn.f32x2 %0, %1, %2;" : "=l"(x0.y) : "l"(x0.y), "l"(kk));
            asm("mul.rn.f32x2 %0, %1, %2;" : "=l"(x1.x) : "l"(x1.x), "l"(kk));
            asm("mul.rn.f32x2 %0, %1, %2;" : "=l"(x1.y) : "l"(x1.y), "l"(kk));
            A0[u] = x0; A1[u] = x1;
        }
    }
    __shared__ float4 s_tile[CHUNK * 8];         // 32 KB
    int tc = min(CHUNK, nCol - cBase);
    for (int g0 = tid; g0 < tc; g0 += 128) {
        int g = cBase + g0;
        const float4* src = (g < posCnt) ? &g_posF[img][g][0]
                                         : &g_negF[img][g - posCnt][0];
        #pragma unroll
        for (int u = 0; u < 8; ++u) s_tile[g0*8 + u] = src[u];
    }
    __syncthreads();

    float num0 = 0.f, neg0 = 0.f, num1 = 0.f, neg1 = 0.f;
    #pragma unroll 2
    for (int j = 0; j < tc; ++j) {
        const ulonglong2* cv = reinterpret_cast<const ulonglong2*>(&s_tile[j*8]);
        ull s00 = 0ull, s01 = 0ull, s10 = 0ull, s11 = 0ull;
        #pragma unroll
        for (int u = 0; u < 8; ++u) {
            ulonglong2 v = cv[u];
            asm("fma.rn.f32x2 %0, %1, %2, %0;" : "+l"(s00) : "l"(A0[u].x), "l"(v.x));
            asm("fma.rn.f32x2 %0, %1, %2, %0;" : "+l"(s01) : "l"(A0[u].y), "l"(v.y));
            asm("fma.rn.f32x2 %0, %1, %2, %0;" : "+l"(s10) : "l"(A1[u].x), "l"(v.x));
            asm("fma.rn.f32x2 %0, %1, %2, %0;" : "+l"(s11) : "l"(A1[u].y), "l"(v.y));
        }
        ull t0, t1;
        asm("add.rn.f32x2 %0, %1, %2;" : "=l"(t0) : "l"(s00), "l"(s01));
        asm("add.rn.f32x2 %0, %1, %2;" : "=l"(t1) : "l"(s10), "l"(s11));
        float d0 = __uint_as_float((unsigned)t0) + __uint_as_float((unsigned)(t0 >> 32));
        float d1 = __uint_as_float((unsigned)t1) + __uint_as_float((unsigned)(t1 >> 32));
        float e0 = exp2f(d0);                    // logits pre-scaled
        float e1 = exp2f(d1);
        int jg = cBase + j;
        if (jg < posCnt) {
            if (jg != a0) num0 += e0;
            if (jg != a1) num1 += e1;
        } else { neg0 += e0; neg1 += e1; }
    }
    if (a0 < posCnt) { atomicAdd(&g_acc[img][a0][0], num0); atomicAdd(&g_acc[img][a0][1], neg0); }
    if (a1 < posCnt) { atomicAdd(&g_acc[img][a1][0], num1); atomicAdd(&g_acc[img][a1][1], neg1); }
}

// ---------------- stage 6: per-image reduction + final (fused) --------------
__global__ void k_redfinal(float* out) {
    int img = blockIdx.x;
    int tid = threadIdx.x;
    int posCnt = min(g_cnt[img][0], PCAP);
    int negCnt = min(g_cnt[img][1], NCAP);
    float sum = 0.f, cnt = 0.f;
    for (int a = tid; a < posCnt; a += 256) {
        float num = g_acc[img][a][0];
        float neg = g_acc[img][a][1];
        if (num > 0.f) { sum += log1pf(neg / num); cnt += 1.f; }  // -log(num/(num+neg))
    }
    __shared__ float ss[256], sc[256];
    ss[tid] = sum; sc[tid] = cnt;
    __syncthreads();
    for (int o = 128; o > 0; o >>= 1) {
        if (tid < o) { ss[tid] += ss[tid + o]; sc[tid] += sc[tid + o]; }
        __syncthreads();
    }
    if (tid == 0) {
        g_imgLoss[img]  = ss[0] / fmaxf(sc[0], 1.f);
        g_imgValid[img] = (posCnt >= 2 && negCnt > 0 && sc[0] > 0.f) ? 1 : 0;
        __threadfence();
        int ticket = atomicAdd(&g_done, 1);
        if (ticket == NB - 1) {                   // last image finalizes
            float v0 = g_imgValid[0] ? 1.f : 0.f;
            float v1 = g_imgValid[1] ? 1.f : 0.f;
            float s = g_imgLoss[0]*v0 + g_imgLoss[1]*v1;
            float tot = s / fmaxf(v0 + v1, 1.f);
            out[0] = (v0 + v1 > 0.f) ? tot : 0.f;
        }
    }
}

// ---------------- launch ----------------
extern "C" void kernel_launch(void* const* d_in, const int* in_sizes, int n_in,
                              void* d_out, int out_size) {
    const float* feats = (const float*)d_in[0];
    const int*   lab   = (const int*)d_in[1];
    (void)in_sizes; (void)n_in; (void)out_size;

    k_pack  <<<NROWS/8, 256>>>(lab);
    k_dilh  <<<NROWS*4/256, 256>>>();
    k_demit <<<NROWS*4/256, 256>>>();
    k_gather<<<(NB*COLCAP + 255)/256, 256>>>(feats);
    k_main  <<<dim3(PCAP/256, NYCH, NB), 128>>>();
    k_redfinal<<<NB, 256>>>((float*)d_out);
}

// round 8
// speedup vs baseline: 2.8583x; 1.5351x over previous
#include <cuda_runtime.h>
#include <cuda_bf16.h>
#include <cstdint>

#define NVOX   (64*128*128)
#define NB     2
#define NC     32
#define PCAP   2048
#define NCAP   12288
#define COLCAP (PCAP+NCAP)         // 14336
#define MTILE  64                  // anchors per block
#define NTILE  128                 // columns per block
#define NXCH   (PCAP/MTILE)        // 32
#define NYCH   (COLCAP/NTILE)      // 112
#define NROWS  (NB*64*128)         // 16384
#define SASTR  36                  // padded word stride (36 mod 32 = 4 -> conflict-free quads)

typedef unsigned long long ull;

// ---------------- device scratch (no allocations allowed) ----------------
__device__ unsigned g_bfm[NROWS*4];
__device__ unsigned g_bw[NROWS*4];
__device__ unsigned g_bh[NROWS*4];
__device__ int    g_cnt[NB][2];
__device__ int    g_done;
__device__ int    g_posIdx[NB][PCAP];
__device__ int    g_negIdx[NB][NCAP];
__device__ uint4  g_B[NB][COLCAP][8];     // per row: words 0-15 = hi bf16x2, 16-31 = lo
__device__ float  g_acc[NB][PCAP][2];     // per-anchor (num, neg)
__device__ float  g_imgLoss[NB];
__device__ int    g_imgValid[NB];

__device__ __forceinline__ int bidx(int pl, int h, int w) { return pl*512 + h*4 + w; }
__device__ __forceinline__ unsigned packbf(__nv_bfloat16 a, __nv_bfloat16 b) {
    __nv_bfloat162 t; t.x = a; t.y = b;
    return *reinterpret_cast<unsigned*>(&t);
}
__device__ __forceinline__ float ex2f(float x) {
    float r; asm("ex2.approx.ftz.f32 %0, %1;" : "=f"(r) : "f"(x)); return r;
}

// ---------------- stage 1: fg bitmask + W-dilation (fused) ------------------
__global__ void k_pack(const int* __restrict__ lab) {
    int warp = threadIdx.x >> 5, lane = threadIdx.x & 31;
    int row  = blockIdx.x * 8 + warp;
    __shared__ unsigned srow[8][4];
    if (lane < 4) srow[warp][lane] = 0;
    __syncwarp();
    int4 l = *reinterpret_cast<const int4*>(lab + (size_t)row*128 + lane*4);
    unsigned nib = (unsigned)(l.x > 0) | ((unsigned)(l.y > 0) << 1)
                 | ((unsigned)(l.z > 0) << 2) | ((unsigned)(l.w > 0) << 3);
    if (nib) atomicOr(&srow[warp][lane >> 3], nib << ((lane & 7) * 4));
    __syncwarp();
    if (lane < 4) {
        unsigned f  = srow[warp][lane];
        unsigned fl = (lane > 0) ? srow[warp][lane-1] : 0u;
        unsigned fr = (lane < 3) ? srow[warp][lane+1] : 0u;
        unsigned dil = f;
        #pragma unroll
        for (int k = 1; k <= 5; ++k) {
            dil |= __funnelshift_r(f, fr, k);
            dil |= __funnelshift_l(fl, f, k);
        }
        g_bfm[row*4 + lane] = f;
        g_bw[row*4 + lane] = dil;
    }
    if (blockIdx.x < 32) ((float*)g_acc)[blockIdx.x * 256 + threadIdx.x] = 0.f;
    if (blockIdx.x == 0 && threadIdx.x == 0) {
        g_cnt[0][0] = g_cnt[0][1] = g_cnt[1][0] = g_cnt[1][1] = 0;
        g_done = 0;
    }
}

// ---------------- stage 2: H-dilation --------------------------------------
__global__ void k_dilh() {
    int t = blockIdx.x * 256 + threadIdx.x;
    int w  = t & 3;
    int h  = (t >> 2) & 127;
    int pl = t >> 9;
    unsigned acc = 0;
    #pragma unroll
    for (int k = -5; k <= 5; ++k) {
        int hh = h + k;
        if ((unsigned)hh < 128u) acc |= g_bw[bidx(pl, hh, w)];
    }
    g_bh[bidx(pl, h, w)] = acc;
}

// ---------------- stage 3: D-dilation + rim + atomic emit -------------------
__global__ void k_demit() {
    int t = blockIdx.x * 256 + threadIdx.x;
    int w   = t & 3;
    int h   = (t >> 2) & 127;
    int pl  = t >> 9;
    int img = pl >> 6, d = pl & 63;
    unsigned acc = 0;
    #pragma unroll
    for (int k = -5; k <= 5; ++k) {
        int dd = d + k;
        if ((unsigned)dd < 64u) acc |= g_bh[bidx(img*64 + dd, h, w)];
    }
    unsigned fgw = g_bfm[bidx(pl, h, w)];
    unsigned rim = acc & ~fgw;
    int vbase = d*16384 + h*128 + w*32;
    if (fgw) {
        int c = __popc(fgw);
        int base = atomicAdd(&g_cnt[img][0], c);
        unsigned m = fgw;
        while (m) {
            int b = __ffs(m) - 1; m &= m - 1;
            if (base < PCAP) g_posIdx[img][base] = vbase + b;
            base++;
        }
    }
    if (rim) {
        int c = __popc(rim);
        int base = atomicAdd(&g_cnt[img][1], c);
        unsigned m = rim;
        while (m) {
            int b = __ffs(m) - 1; m &= m - 1;
            if (base < NCAP) g_negIdx[img][base] = vbase + b;
            base++;
        }
    }
}

// ---------------- stage 4: gather + normalize + bf16 hi/lo split ------------
// 1 thread/row, 32 strided loads in flight. Row -> g_B[col]:
//   words 0-15: hi bf16x2 (channels 2w,2w+1); words 16-31: lo residual.
__global__ void k_gather(const float* __restrict__ feats) {
    int t = blockIdx.x * 256 + threadIdx.x;
    int img = t / COLCAP;
    if (img >= NB) return;
    int s = t - img * COLCAP;
    int posCnt = min(g_cnt[img][0], PCAP);
    int negCnt = min(g_cnt[img][1], NCAP);
    int n, col;
    if (s < PCAP) {
        if (s >= posCnt) return;
        n = g_posIdx[img][s]; col = s;
    } else {
        int j = s - PCAP;
        if (j >= negCnt) return;
        n = g_negIdx[img][j]; col = posCnt + j;
    }
    const float* f = feats + (size_t)img * NC * NVOX + n;
    float v[NC]; float ss = 0.f;
    #pragma unroll
    for (int c = 0; c < NC; ++c) { v[c] = __ldg(f + (size_t)c * NVOX); ss += v[c]*v[c]; }
    float sc = 1.0f / fmaxf(sqrtf(ss), 1e-12f);

    unsigned hw[16], lw[16];
    #pragma unroll
    for (int w = 0; w < 16; ++w) {
        float x0 = v[2*w] * sc, x1 = v[2*w+1] * sc;
        __nv_bfloat16 h0 = __float2bfloat16(x0);
        __nv_bfloat16 h1 = __float2bfloat16(x1);
        __nv_bfloat16 l0 = __float2bfloat16(x0 - __bfloat162float(h0));
        __nv_bfloat16 l1 = __float2bfloat16(x1 - __bfloat162float(h1));
        hw[w] = packbf(h0, h1);
        lw[w] = packbf(l0, l1);
    }
    uint4* dst = &g_B[img][col][0];
    #pragma unroll
    for (int u = 0; u < 4; ++u) {
        dst[u]     = make_uint4(hw[4*u], hw[4*u+1], hw[4*u+2], hw[4*u+3]);
        dst[u + 4] = make_uint4(lw[4*u], lw[4*u+1], lw[4*u+2], lw[4*u+3]);
    }
}

// ---------------- stage 5: warp-MMA bf16-split GEMM + softmax epilogue ------
// Block: M=64 anchors x N=128 cols, 8 warps (wm = wid&1 -> 32 rows,
// wn = wid>>1 -> 32 cols).  mma.sync m16n8k16 bf16, 6 k-steps implementing
// ah*bh + al*bh + ah*bl (drops al*bl ~2^-16).  Logit scaled by
// (1/TAU)*log2(e) in the epilogue, then ex2.approx -> masked num/neg sums
// -> quad shfl reduce -> atomicAdd into g_acc.
__global__ void __launch_bounds__(256) k_mma() {
    int img = blockIdx.z;
    int posCnt = min(g_cnt[img][0], PCAP);
    int negCnt = min(g_cnt[img][1], NCAP);
    int nCol = posCnt + negCnt;
    int aBase = blockIdx.x * MTILE;
    int cBase = blockIdx.y * NTILE;
    if (aBase >= posCnt || cBase >= nCol) return;

    __shared__ __align__(16) unsigned sA[MTILE * SASTR];   //  9216 B
    __shared__ __align__(16) unsigned sB[NTILE * SASTR];   // 18432 B

    int t = threadIdx.x;
    // fill A tile (anchor rows = pos region of g_B)
    #pragma unroll
    for (int i = t; i < MTILE*8; i += 256) {
        int row = i >> 3, u = i & 7;
        uint4 q = g_B[img][aBase + row][u];
        *reinterpret_cast<uint4*>(&sA[row*SASTR + u*4]) = q;
    }
    // fill B tile
    #pragma unroll
    for (int i = t; i < NTILE*8; i += 256) {
        int col = i >> 3, u = i & 7;
        uint4 q = g_B[img][cBase + col][u];
        *reinterpret_cast<uint4*>(&sB[col*SASTR + u*4]) = q;
    }
    __syncthreads();

    int wid = t >> 5, lane = t & 31;
    int wm = wid & 1, wn = wid >> 1;
    int gq = lane >> 2, tq = lane & 3;

    float d[2][4][4];
    #pragma unroll
    for (int mt = 0; mt < 2; ++mt)
        #pragma unroll
        for (int nt = 0; nt < 4; ++nt)
            #pragma unroll
            for (int r = 0; r < 4; ++r) d[mt][nt][r] = 0.f;

    // word-base tables: steps = (Ahi,Bhi)(0-15ch),(Alo,Bhi),(Ahi,Blo)
    const int awb[6] = {0, 8, 16, 24, 0, 8};
    const int bwb[6] = {0, 8, 0, 8, 16, 24};
    int baseA = (wm*32 + gq) * SASTR + tq;       // + mt*16*SASTR, + aw, (+4), (+8*SASTR)
    int baseB = (wn*32 + gq) * SASTR + tq;       // + nt*8*SASTR,  + bw, (+4)

    #pragma unroll
    for (int ks = 0; ks < 6; ++ks) {
        int aw = awb[ks], bw = bwb[ks];
        unsigned a[2][4], b[4][2];
        #pragma unroll
        for (int mt = 0; mt < 2; ++mt) {
            int p = baseA + mt*16*SASTR + aw;
            a[mt][0] = sA[p];
            a[mt][1] = sA[p + 8*SASTR];
            a[mt][2] = sA[p + 4];
            a[mt][3] = sA[p + 8*SASTR + 4];
        }
        #pragma unroll
        for (int nt = 0; nt < 4; ++nt) {
            int p = baseB + nt*8*SASTR + bw;
            b[nt][0] = sB[p];
            b[nt][1] = sB[p + 4];
        }
        #pragma unroll
        for (int mt = 0; mt < 2; ++mt)
            #pragma unroll
            for (int nt = 0; nt < 4; ++nt)
                asm volatile(
                    "mma.sync.aligned.m16n8k16.row.col.f32.bf16.bf16.f32 "
                    "{%0,%1,%2,%3}, {%4,%5,%6,%7}, {%8,%9}, {%0,%1,%2,%3};"
                    : "+f"(d[mt][nt][0]), "+f"(d[mt][nt][1]),
                      "+f"(d[mt][nt][2]), "+f"(d[mt][nt][3])
                    : "r"(a[mt][0]), "r"(a[mt][1]), "r"(a[mt][2]), "r"(a[mt][3]),
                      "r"(b[nt][0]), "r"(b[nt][1]));
    }

    const float SCALE = 14.4269504088896340f;    // (1/TAU) * log2(e)
    #pragma unroll
    for (int mt = 0; mt < 2; ++mt) {
        int r0 = aBase + wm*32 + mt*16 + gq;
        int r1 = r0 + 8;
        float n0 = 0.f, g0 = 0.f, n1 = 0.f, g1 = 0.f;
        #pragma unroll
        for (int nt = 0; nt < 4; ++nt) {
            int c = cBase + wn*32 + nt*8 + 2*tq;
            #pragma unroll
            for (int r = 0; r < 4; ++r) {
                int cg = c + (r & 1);
                int rg = (r < 2) ? r0 : r1;
                if (cg < nCol) {
                    float e = ex2f(d[mt][nt][r] * SCALE);
                    if (cg < posCnt) {
                        if (cg != rg) { if (r < 2) n0 += e; else n1 += e; }
                    } else { if (r < 2) g0 += e; else g1 += e; }
                }
            }
        }
        #pragma unroll
        for (int off = 1; off <= 2; off <<= 1) {
            n0 += __shfl_xor_sync(0xffffffffu, n0, off);
            g0 += __shfl_xor_sync(0xffffffffu, g0, off);
            n1 += __shfl_xor_sync(0xffffffffu, n1, off);
            g1 += __shfl_xor_sync(0xffffffffu, g1, off);
        }
        if (tq == 0) {
            if (r0 < posCnt) { atomicAdd(&g_acc[img][r0][0], n0); atomicAdd(&g_acc[img][r0][1], g0); }
            if (r1 < posCnt) { atomicAdd(&g_acc[img][r1][0], n1); atomicAdd(&g_acc[img][r1][1], g1); }
        }
    }
}

// ---------------- stage 6: per-image reduction + final (fused) --------------
__global__ void k_redfinal(float* out) {
    int img = blockIdx.x;
    int tid = threadIdx.x;
    int posCnt = min(g_cnt[img][0], PCAP);
    int negCnt = min(g_cnt[img][1], NCAP);
    float sum = 0.f, cnt = 0.f;
    for (int a = tid; a < posCnt; a += 256) {
        float num = g_acc[img][a][0];
        float neg = g_acc[img][a][1];
        if (num > 0.f) { sum += log1pf(neg / num); cnt += 1.f; }
    }
    __shared__ float ss[256], sc[256];
    ss[tid] = sum; sc[tid] = cnt;
    __syncthreads();
    for (int o = 128; o > 0; o >>= 1) {
        if (tid < o) { ss[tid] += ss[tid + o]; sc[tid] += sc[tid + o]; }
        __syncthreads();
    }
    if (tid == 0) {
        g_imgLoss[img]  = ss[0] / fmaxf(sc[0], 1.f);
        g_imgValid[img] = (posCnt >= 2 && negCnt > 0 && sc[0] > 0.f) ? 1 : 0;
        __threadfence();
        int ticket = atomicAdd(&g_done, 1);
        if (ticket == NB - 1) {
            float v0 = g_imgValid[0] ? 1.f : 0.f;
            float v1 = g_imgValid[1] ? 1.f : 0.f;
            float s = g_imgLoss[0]*v0 + g_imgLoss[1]*v1;
            float tot = s / fmaxf(v0 + v1, 1.f);
            out[0] = (v0 + v1 > 0.f) ? tot : 0.f;
        }
    }
}

// ---------------- launch ----------------
extern "C" void kernel_launch(void* const* d_in, const int* in_sizes, int n_in,
                              void* d_out, int out_size) {
    const float* feats = (const float*)d_in[0];
    const int*   lab   = (const int*)d_in[1];
    (void)in_sizes; (void)n_in; (void)out_size;

    k_pack  <<<NROWS/8, 256>>>(lab);
    k_dilh  <<<NROWS*4/256, 256>>>();
    k_demit <<<NROWS*4/256, 256>>>();
    k_gather<<<(NB*COLCAP + 255)/256, 256>>>(feats);
    k_mma   <<<dim3(NXCH, NYCH, NB), 256>>>();
    k_redfinal<<<NB, 256>>>((float*)d_out);
}

// round 11
// speedup vs baseline: 2.8602x; 1.0006x over previous
#include <cuda_runtime.h>
#include <cuda_bf16.h>
#include <cstdint>

#define NVOX   (64*128*128)
#define NB     2
#define NC     32
#define PCAP   2048
#define NCAP   12288
#define COLCAP (PCAP+NCAP)         // 14336
#define MTILE  128                 // anchors per block
#define NTILE  128                 // columns per block
#define NXCH   (PCAP/MTILE)        // 16
#define NYCH   (COLCAP/NTILE)      // 112
#define NROWS  (NB*64*128)         // 16384

typedef unsigned long long ull;

// ---------------- device scratch (no allocations allowed) ----------------
__device__ unsigned g_bfm[NROWS*4];
__device__ unsigned g_bw[NROWS*4];
__device__ unsigned g_bh[NROWS*4];
__device__ int    g_cnt[NB][2];
__device__ int    g_done;
__device__ int    g_posIdx[NB][PCAP];
__device__ int    g_negIdx[NB][NCAP];
// per row: 8 uint4 units; data-unit u stored at slot u^(col&7) (XOR swizzle).
// data units 0-3 = hi bf16x2 words 0-15 (ch 0-31), units 4-7 = lo residual.
__device__ uint4  g_B[NB][COLCAP][8];
__device__ float  g_acc[NB][PCAP][2];     // per-anchor (num, neg)
__device__ float  g_imgLoss[NB];
__device__ int    g_imgValid[NB];

__device__ __forceinline__ int bidx(int pl, int h, int w) { return pl*512 + h*4 + w; }
__device__ __forceinline__ unsigned packbf(__nv_bfloat16 a, __nv_bfloat16 b) {
    __nv_bfloat162 t; t.x = a; t.y = b;
    return *reinterpret_cast<unsigned*>(&t);
}
__device__ __forceinline__ float ex2f(float x) {
    float r; asm("ex2.approx.ftz.f32 %0, %1;" : "=f"(r) : "f"(x)); return r;
}

// ---------------- stage 1: fg bitmask + W-dilation (fused) ------------------
__global__ void k_pack(const int* __restrict__ lab) {
    int warp = threadIdx.x >> 5, lane = threadIdx.x & 31;
    int row  = blockIdx.x * 8 + warp;
    __shared__ unsigned srow[8][4];
    if (lane < 4) srow[warp][lane] = 0;
    __syncwarp();
    int4 l = *reinterpret_cast<const int4*>(lab + (size_t)row*128 + lane*4);
    unsigned nib = (unsigned)(l.x > 0) | ((unsigned)(l.y > 0) << 1)
                 | ((unsigned)(l.z > 0) << 2) | ((unsigned)(l.w > 0) << 3);
    if (nib) atomicOr(&srow[warp][lane >> 3], nib << ((lane & 7) * 4));
    __syncwarp();
    if (lane < 4) {
        unsigned f  = srow[warp][lane];
        unsigned fl = (lane > 0) ? srow[warp][lane-1] : 0u;
        unsigned fr = (lane < 3) ? srow[warp][lane+1] : 0u;
        unsigned dil = f;
        #pragma unroll
        for (int k = 1; k <= 5; ++k) {
            dil |= __funnelshift_r(f, fr, k);
            dil |= __funnelshift_l(fl, f, k);
        }
        g_bfm[row*4 + lane] = f;
        g_bw[row*4 + lane] = dil;
    }
    if (blockIdx.x < 32) ((float*)g_acc)[blockIdx.x * 256 + threadIdx.x] = 0.f;
    if (blockIdx.x == 0 && threadIdx.x == 0) {
        g_cnt[0][0] = g_cnt[0][1] = g_cnt[1][0] = g_cnt[1][1] = 0;
        g_done = 0;
    }
}

// ---------------- stage 2: H-dilation --------------------------------------
__global__ void k_dilh() {
    int t = blockIdx.x * 256 + threadIdx.x;
    int w  = t & 3;
    int h  = (t >> 2) & 127;
    int pl = t >> 9;
    unsigned acc = 0;
    #pragma unroll
    for (int k = -5; k <= 5; ++k) {
        int hh = h + k;
        if ((unsigned)hh < 128u) acc |= g_bw[bidx(pl, hh, w)];
    }
    g_bh[bidx(pl, h, w)] = acc;
}

// ---------------- stage 3: D-dilation + rim + atomic emit -------------------
__global__ void k_demit() {
    int t = blockIdx.x * 256 + threadIdx.x;
    int w   = t & 3;
    int h   = (t >> 2) & 127;
    int pl  = t >> 9;
    int img = pl >> 6, d = pl & 63;
    unsigned acc = 0;
    #pragma unroll
    for (int k = -5; k <= 5; ++k) {
        int dd = d + k;
        if ((unsigned)dd < 64u) acc |= g_bh[bidx(img*64 + dd, h, w)];
    }
    unsigned fgw = g_bfm[bidx(pl, h, w)];
    unsigned rim = acc & ~fgw;
    int vbase = d*16384 + h*128 + w*32;
    if (fgw) {
        int c = __popc(fgw);
        int base = atomicAdd(&g_cnt[img][0], c);
        unsigned m = fgw;
        while (m) {
            int b = __ffs(m) - 1; m &= m - 1;
            if (base < PCAP) g_posIdx[img][base] = vbase + b;
            base++;
        }
    }
    if (rim) {
        int c = __popc(rim);
        int base = atomicAdd(&g_cnt[img][1], c);
        unsigned m = rim;
        while (m) {
            int b = __ffs(m) - 1; m &= m - 1;
            if (base < NCAP) g_negIdx[img][base] = vbase + b;
            base++;
        }
    }
}

// ---------------- stage 4: gather + normalize + bf16 hi/lo split ------------
// 2 threads/row (lanes 2i, 2i+1): 16 channel loads each, norm partial combined
// with one shfl_xor (no barriers).  Writes 4 uint4 units each with XOR swizzle.
__global__ void k_gather(const float* __restrict__ feats) {
    int t = blockIdx.x * 256 + threadIdx.x;
    int rsel = t >> 1, half = t & 1;
    int img = rsel / COLCAP;
    bool valid = (img < NB);
    int s = rsel - img * COLCAP;
    int n = 0, col = 0;
    if (valid) {
        int posCnt = min(g_cnt[img][0], PCAP);
        int negCnt = min(g_cnt[img][1], NCAP);
        if (s < PCAP) {
            valid = (s < posCnt);
            n = valid ? g_posIdx[img][s] : 0;
            col = s;
        } else {
            int j = s - PCAP;
            valid = (j < negCnt);
            n = valid ? g_negIdx[img][j] : 0;
            col = posCnt + j;
        }
    } else { img = 0; }
    const float* f = feats + (size_t)img * NC * NVOX + (size_t)half * 16 * NVOX + n;
    float v[16]; float ss = 0.f;
    #pragma unroll
    for (int k = 0; k < 16; ++k) { v[k] = __ldg(f + (size_t)k * NVOX); ss += v[k]*v[k]; }
    ss += __shfl_xor_sync(0xffffffffu, ss, 1);   // combine halves (pair in-warp)
    float sc = 1.0f / fmaxf(sqrtf(ss), 1e-12f);

    if (!valid) return;
    unsigned hw[8], lw[8];
    #pragma unroll
    for (int w = 0; w < 8; ++w) {
        float x0 = v[2*w] * sc, x1 = v[2*w+1] * sc;
        __nv_bfloat16 h0 = __float2bfloat16(x0);
        __nv_bfloat16 h1 = __float2bfloat16(x1);
        __nv_bfloat16 l0 = __float2bfloat16(x0 - __bfloat162float(h0));
        __nv_bfloat16 l1 = __float2bfloat16(x1 - __bfloat162float(h1));
        hw[w] = packbf(h0, h1);
        lw[w] = packbf(l0, l1);
    }
    int perm = col & 7;
    uint4* dst = &g_B[img][col][0];
    #pragma unroll
    for (int u = 0; u < 2; ++u) {
        dst[(half*2 + u)     ^ perm] = make_uint4(hw[4*u], hw[4*u+1], hw[4*u+2], hw[4*u+3]);
        dst[(4 + half*2 + u) ^ perm] = make_uint4(lw[4*u], lw[4*u+1], lw[4*u+2], lw[4*u+3]);
    }
}

// ---------------- stage 5: warp-MMA bf16-split GEMM + softmax epilogue ------
// Block: 128 anchors x 128 cols, 8 warps: wm=wid&3 (32 rows), wn=wid>>2
// (64 cols).  XOR-swizzled SMEM (32 words/row, no padding): fragment word w
// lives at unit (w>>2)^(row&7); '+4 word' variants are addr^4 (unit base even).
// 6 k-steps: ah*bh + al*bh + ah*bl.  Epilogue: scale*log2e, ex2, masked sums,
// quad shfl reduce, atomicAdd into g_acc.
__global__ void __launch_bounds__(256, 2) k_mma() {
    int img = blockIdx.z;
    int posCnt = min(g_cnt[img][0], PCAP);
    int negCnt = min(g_cnt[img][1], NCAP);
    int nCol = posCnt + negCnt;
    int aBase = blockIdx.x * MTILE;
    int cBase = blockIdx.y * NTILE;
    if (aBase >= posCnt || cBase >= nCol) return;

    __shared__ __align__(16) unsigned sA[MTILE * 32];   // 16 KB
    __shared__ __align__(16) unsigned sB[NTILE * 32];   // 16 KB

    int t = threadIdx.x;
    {   // linear tile fill (swizzle already applied in gmem)
        uint4*       a4 = reinterpret_cast<uint4*>(sA);
        uint4*       b4 = reinterpret_cast<uint4*>(sB);
        const uint4* ga = &g_B[img][aBase][0];
        const uint4* gb = &g_B[img][cBase][0];
        #pragma unroll
        for (int i = 0; i < 4; ++i) {
            a4[t + 256*i] = ga[t + 256*i];
            b4[t + 256*i] = gb[t + 256*i];
        }
    }
    __syncthreads();

    int wid = t >> 5, lane = t & 31;
    int wm = wid & 3, wn = wid >> 2;
    int gq = lane >> 2, tq = lane & 3;
    int rbase = wm * 32, cbw = wn * 64;

    float d[2][8][4];
    #pragma unroll
    for (int mt = 0; mt < 2; ++mt)
        #pragma unroll
        for (int nt = 0; nt < 8; ++nt)
            #pragma unroll
            for (int r = 0; r < 4; ++r) d[mt][nt][r] = 0.f;

    const int awb[6] = {0, 8, 16, 24, 0, 8};   // A word bases: hi,hi,lo,lo,hi,hi
    const int bwb[6] = {0, 8, 0, 8, 16, 24};   // B word bases: hi,hi,hi,hi,lo,lo

    #pragma unroll
    for (int ks = 0; ks < 6; ++ks) {
        int ua = (((awb[ks] >> 2) ^ gq) << 2) + tq;
        int ub = (((bwb[ks] >> 2) ^ gq) << 2) + tq;
        unsigned a[2][4];
        #pragma unroll
        for (int mt = 0; mt < 2; ++mt) {
            int p = (rbase + mt*16 + gq) * 32 + ua;
            a[mt][0] = sA[p];
            a[mt][1] = sA[p + 256];            // +8 rows
            a[mt][2] = sA[p ^ 4];              // word +4 (unit^1)
            a[mt][3] = sA[(p + 256) ^ 4];
        }
        #pragma unroll
        for (int nt = 0; nt < 8; ++nt) {
            int p = (cbw + nt*8 + gq) * 32 + ub;
            unsigned b0 = sB[p], b1 = sB[p ^ 4];
            #pragma unroll
            for (int mt = 0; mt < 2; ++mt)
                asm volatile(
                    "mma.sync.aligned.m16n8k16.row.col.f32.bf16.bf16.f32 "
                    "{%0,%1,%2,%3}, {%4,%5,%6,%7}, {%8,%9}, {%0,%1,%2,%3};"
                    : "+f"(d[mt][nt][0]), "+f"(d[mt][nt][1]),
                      "+f"(d[mt][nt][2]), "+f"(d[mt][nt][3])
                    : "r"(a[mt][0]), "r"(a[mt][1]), "r"(a[mt][2]), "r"(a[mt][3]),
                      "r"(b0), "r"(b1));
        }
    }

    const float SCALE = 14.4269504088896340f;    // (1/TAU) * log2(e)
    #pragma unroll
    for (int mt = 0; mt < 2; ++mt) {
        int r0 = aBase + rbase + mt*16 + gq;
        int r1 = r0 + 8;
        float n0 = 0.f, g0 = 0.f, n1 = 0.f, g1 = 0.f;
        #pragma unroll
        for (int nt = 0; nt < 8; ++nt) {
            int c = cBase + cbw + nt*8 + 2*tq;
            #pragma unroll
            for (int r = 0; r < 4; ++r) {
                int cg = c + (r & 1);
                int rg = (r < 2) ? r0 : r1;
                if (cg < nCol) {
                    float e = ex2f(d[mt][nt][r] * SCALE);
                    if (cg < posCnt) {
                        if (cg != rg) { if (r < 2) n0 += e; else n1 += e; }
                    } else { if (r < 2) g0 += e; else g1 += e; }
                }
            }
        }
        #pragma unroll
        for (int off = 1; off <= 2; off <<= 1) {
            n0 += __shfl_xor_sync(0xffffffffu, n0, off);
            g0 += __shfl_xor_sync(0xffffffffu, g0, off);
            n1 += __shfl_xor_sync(0xffffffffu, n1, off);
            g1 += __shfl_xor_sync(0xffffffffu, g1, off);
        }
        if (tq == 0) {
            if (r0 < posCnt) { atomicAdd(&g_acc[img][r0][0], n0); atomicAdd(&g_acc[img][r0][1], g0); }
            if (r1 < posCnt) { atomicAdd(&g_acc[img][r1][0], n1); atomicAdd(&g_acc[img][r1][1], g1); }
        }
    }
}

// ---------------- stage 6: per-image reduction + final (fused) --------------
__global__ void k_redfinal(float* out) {
    int img = blockIdx.x;
    int tid = threadIdx.x;
    int posCnt = min(g_cnt[img][0], PCAP);
    int negCnt = min(g_cnt[img][1], NCAP);
    float sum = 0.f, cnt = 0.f;
    for (int a = tid; a < posCnt; a += 256) {
        float num = g_acc[img][a][0];
        float neg = g_acc[img][a][1];
        if (num > 0.f) { sum += log1pf(neg / num); cnt += 1.f; }
    }
    __shared__ float ss[256], sc[256];
    ss[tid] = sum; sc[tid] = cnt;
    __syncthreads();
    for (int o = 128; o > 0; o >>= 1) {
        if (tid < o) { ss[tid] += ss[tid + o]; sc[tid] += sc[tid + o]; }
        __syncthreads();
    }
    if (tid == 0) {
        g_imgLoss[img]  = ss[0] / fmaxf(sc[0], 1.f);
        g_imgValid[img] = (posCnt >= 2 && negCnt > 0 && sc[0] > 0.f) ? 1 : 0;
        __threadfence();
        int ticket = atomicAdd(&g_done, 1);
        if (ticket == NB - 1) {
            float v0 = g_imgValid[0] ? 1.f : 0.f;
            float v1 = g_imgValid[1] ? 1.f : 0.f;
            float s = g_imgLoss[0]*v0 + g_imgLoss[1]*v1;
            float tot = s / fmaxf(v0 + v1, 1.f);
            out[0] = (v0 + v1 > 0.f) ? tot : 0.f;
        }
    }
}

// ---------------- launch ----------------
extern "C" void kernel_launch(void* const* d_in, const int* in_sizes, int n_in,
                              void* d_out, int out_size) {
    const float* feats = (const float*)d_in[0];
    const int*   lab   = (const int*)d_in[1];
    (void)in_sizes; (void)n_in; (void)out_size;

    k_pack  <<<NROWS/8, 256>>>(lab);
    k_dilh  <<<NROWS*4/256, 256>>>();
    k_demit <<<NROWS*4/256, 256>>>();
    k_gather<<<NB*COLCAP*2/256, 256>>>(feats);
    k_mma   <<<dim3(NXCH, NYCH, NB), 256>>>();
    k_redfinal<<<NB, 256>>>((float*)d_out);
}